// round 2
// baseline (speedup 1.0000x reference)
#include <cuda_runtime.h>
#include <cstddef>

// Problem constants
#define BATCH 4
#define SEQ   2048
#define CDIM  2048
#define HDIM  128

// ---------------- scratch (allocation-free: __device__ globals) -------------
__device__ float g_q[BATCH * SEQ * HDIM];
__device__ float g_k[BATCH * SEQ * HDIM];
__device__ float g_v[BATCH * SEQ * HDIM];

// ======================= QKV projection =====================================
// out[M,128] = X[M,2048] @ W[2048,128], M = B*T = 8192.
// Block tile: 64 x 128, BK = 16, 256 threads, each thread 4x8 outputs.
#define P_BM 64
#define P_BN 128
#define P_BK 16

__global__ __launch_bounds__(256) void proj_kernel(
    const float* __restrict__ x,
    const float* __restrict__ Wq,
    const float* __restrict__ Wk,
    const float* __restrict__ Wv)
{
    const float* W   = (blockIdx.y == 0) ? Wq : (blockIdx.y == 1) ? Wk : Wv;
    float*       out = (blockIdx.y == 0) ? g_q : (blockIdx.y == 1) ? g_k : g_v;

    __shared__ float As[P_BM][P_BK + 1];    // 64 x 17
    __shared__ float Bs[P_BK][P_BN + 4];    // 16 x 132 (row = 528B, 16B aligned)

    const int tid = threadIdx.x;
    const int tx  = tid & 15;   // 0..15 -> output cols tx*4 and 64+tx*4
    const int ty  = tid >> 4;   // 0..15 -> output rows ty*4..ty*4+3
    const int row0 = blockIdx.x * P_BM;

    float acc[4][8];
    #pragma unroll
    for (int i = 0; i < 4; i++)
        #pragma unroll
        for (int j = 0; j < 8; j++) acc[i][j] = 0.f;

    for (int k0 = 0; k0 < CDIM; k0 += P_BK) {
        // load A tile: 64x16 = 256 float4, one per thread
        {
            const int r  = tid >> 2;        // 0..63
            const int c4 = tid & 3;         // 0..3
            const float4 v = *(const float4*)&x[(size_t)(row0 + r) * CDIM + k0 + c4 * 4];
            As[r][c4 * 4 + 0] = v.x; As[r][c4 * 4 + 1] = v.y;
            As[r][c4 * 4 + 2] = v.z; As[r][c4 * 4 + 3] = v.w;
        }
        // load B tile: 16x128 = 512 float4, two per thread
        #pragma unroll
        for (int i = 0; i < 2; i++) {
            const int idx = tid + i * 256;
            const int r   = idx >> 5;       // 0..15
            const int c4  = idx & 31;       // 0..31
            const float4 v = *(const float4*)&W[(size_t)(k0 + r) * HDIM + c4 * 4];
            *(float4*)&Bs[r][c4 * 4] = v;
        }
        __syncthreads();

        #pragma unroll
        for (int kk = 0; kk < P_BK; kk++) {
            float a[4];
            #pragma unroll
            for (int i = 0; i < 4; i++) a[i] = As[ty * 4 + i][kk];
            const float4 b0 = *(const float4*)&Bs[kk][tx * 4];
            const float4 b1 = *(const float4*)&Bs[kk][64 + tx * 4];
            #pragma unroll
            for (int i = 0; i < 4; i++) {
                acc[i][0] += a[i] * b0.x; acc[i][1] += a[i] * b0.y;
                acc[i][2] += a[i] * b0.z; acc[i][3] += a[i] * b0.w;
                acc[i][4] += a[i] * b1.x; acc[i][5] += a[i] * b1.y;
                acc[i][6] += a[i] * b1.z; acc[i][7] += a[i] * b1.w;
            }
        }
        __syncthreads();
    }

    #pragma unroll
    for (int i = 0; i < 4; i++) {
        const size_t r = (size_t)(row0 + ty * 4 + i) * HDIM;
        float4 o0 = make_float4(acc[i][0], acc[i][1], acc[i][2], acc[i][3]);
        float4 o1 = make_float4(acc[i][4], acc[i][5], acc[i][6], acc[i][7]);
        *(float4*)&out[r + tx * 4]      = o0;
        *(float4*)&out[r + 64 + tx * 4] = o1;
    }
}

// ======================= causal flash attention =============================
// Per block: one (batch, 64-row query tile). Iterate key tiles 0..qt with
// online softmax. 256 threads.
#define A_BM 64
#define A_BN 64
#define QS_STRIDE 129
#define KS_STRIDE 129
#define VS_STRIDE 132
#define SS_STRIDE 65

#define SMEM_FLOATS (A_BM * QS_STRIDE + A_BN * KS_STRIDE + A_BN * VS_STRIDE + A_BM * SS_STRIDE + 3 * A_BM)
#define SMEM_BYTES  (SMEM_FLOATS * 4)

__global__ __launch_bounds__(256) void attn_kernel(float* __restrict__ out)
{
    extern __shared__ float smem[];
    float* Qs      = smem;                           // [64][129]
    float* Ks      = Qs + A_BM * QS_STRIDE;          // [64][129]
    float* Vs      = Ks + A_BN * KS_STRIDE;          // [64][132]
    float* Ss      = Vs + A_BN * VS_STRIDE;          // [64][65]
    float* m_s     = Ss + A_BM * SS_STRIDE;          // [64]
    float* l_s     = m_s + A_BM;                     // [64]
    float* alpha_s = l_s + A_BM;                     // [64]

    const int b  = blockIdx.y;
    const int qt = blockIdx.x;
    const int q0 = qt * A_BM;

    const int tid  = threadIdx.x;
    const int tx   = tid & 15;
    const int ty   = tid >> 4;
    const int lane = tid & 31;
    const int warp = tid >> 5;

    const float* Qg = g_q + (size_t)b * SEQ * HDIM;
    const float* Kg = g_k + (size_t)b * SEQ * HDIM;
    const float* Vg = g_v + (size_t)b * SEQ * HDIM;

    // load Q tile (64 x 128): 2048 float4, 8 per thread
    #pragma unroll
    for (int i = 0; i < 8; i++) {
        const int idx = tid + i * 256;
        const int r   = idx >> 5;
        const int c4  = idx & 31;
        const float4 v = *(const float4*)&Qg[(size_t)(q0 + r) * HDIM + c4 * 4];
        float* dst = &Qs[r * QS_STRIDE + c4 * 4];
        dst[0] = v.x; dst[1] = v.y; dst[2] = v.z; dst[3] = v.w;
    }
    if (tid < A_BM) { m_s[tid] = -1e30f; l_s[tid] = 0.f; }

    float acc[4][8];
    #pragma unroll
    for (int i = 0; i < 4; i++)
        #pragma unroll
        for (int j = 0; j < 8; j++) acc[i][j] = 0.f;

    const float scale = 0.08838834764831843f;   // 1/sqrt(128)
    __syncthreads();

    for (int kt = 0; kt <= qt; kt++) {
        const int k0 = kt * A_BN;
        // load K and V tiles
        #pragma unroll
        for (int i = 0; i < 8; i++) {
            const int idx = tid + i * 256;
            const int r   = idx >> 5;
            const int c4  = idx & 31;
            const float4 kv = *(const float4*)&Kg[(size_t)(k0 + r) * HDIM + c4 * 4];
            float* kd = &Ks[r * KS_STRIDE + c4 * 4];
            kd[0] = kv.x; kd[1] = kv.y; kd[2] = kv.z; kd[3] = kv.w;
            const float4 vv = *(const float4*)&Vg[(size_t)(k0 + r) * HDIM + c4 * 4];
            *(float4*)&Vs[r * VS_STRIDE + c4 * 4] = vv;
        }
        __syncthreads();

        // S = Q K^T * scale  (thread: rows ty*4+i, cols tx*4+j)
        float s[4][4];
        #pragma unroll
        for (int i = 0; i < 4; i++)
            #pragma unroll
            for (int j = 0; j < 4; j++) s[i][j] = 0.f;

        #pragma unroll 4
        for (int kk = 0; kk < HDIM; kk++) {
            float a[4], kb[4];
            #pragma unroll
            for (int i = 0; i < 4; i++) a[i]  = Qs[(ty * 4 + i) * QS_STRIDE + kk];
            #pragma unroll
            for (int j = 0; j < 4; j++) kb[j] = Ks[(tx * 4 + j) * KS_STRIDE + kk];
            #pragma unroll
            for (int i = 0; i < 4; i++)
                #pragma unroll
                for (int j = 0; j < 4; j++) s[i][j] += a[i] * kb[j];
        }

        const bool diag = (kt == qt);
        #pragma unroll
        for (int i = 0; i < 4; i++) {
            const int qi = q0 + ty * 4 + i;
            #pragma unroll
            for (int j = 0; j < 4; j++) {
                const int ki = k0 + tx * 4 + j;
                float val = s[i][j] * scale;
                if (diag && ki > qi) val = -1e30f;
                Ss[(ty * 4 + i) * SS_STRIDE + tx * 4 + j] = val;
            }
        }
        __syncthreads();

        // online softmax: each warp owns 8 rows
        #pragma unroll
        for (int rr = 0; rr < 8; rr++) {
            const int row = warp * 8 + rr;
            float x0 = Ss[row * SS_STRIDE + lane];
            float x1 = Ss[row * SS_STRIDE + 32 + lane];
            float mx = fmaxf(x0, x1);
            #pragma unroll
            for (int off = 16; off > 0; off >>= 1)
                mx = fmaxf(mx, __shfl_xor_sync(0xFFFFFFFFu, mx, off));
            const float m_old = m_s[row];
            const float m_new = fmaxf(m_old, mx);
            const float e0 = __expf(x0 - m_new);
            const float e1 = __expf(x1 - m_new);
            Ss[row * SS_STRIDE + lane]      = e0;
            Ss[row * SS_STRIDE + 32 + lane] = e1;
            float sum = e0 + e1;
            #pragma unroll
            for (int off = 16; off > 0; off >>= 1)
                sum += __shfl_xor_sync(0xFFFFFFFFu, sum, off);
            if (lane == 0) {
                const float alpha = __expf(m_old - m_new);
                alpha_s[row] = alpha;
                l_s[row]     = l_s[row] * alpha + sum;
                m_s[row]     = m_new;
            }
        }
        __syncthreads();

        // rescale accumulators, then O += P @ V
        #pragma unroll
        for (int i = 0; i < 4; i++) {
            const float al = alpha_s[ty * 4 + i];
            #pragma unroll
            for (int j = 0; j < 8; j++) acc[i][j] *= al;
        }
        #pragma unroll 2
        for (int kk = 0; kk < A_BN; kk++) {
            float p[4];
            #pragma unroll
            for (int i = 0; i < 4; i++) p[i] = Ss[(ty * 4 + i) * SS_STRIDE + kk];
            const float4 v0 = *(const float4*)&Vs[kk * VS_STRIDE + tx * 4];
            const float4 v1 = *(const float4*)&Vs[kk * VS_STRIDE + 64 + tx * 4];
            #pragma unroll
            for (int i = 0; i < 4; i++) {
                acc[i][0] += p[i] * v0.x; acc[i][1] += p[i] * v0.y;
                acc[i][2] += p[i] * v0.z; acc[i][3] += p[i] * v0.w;
                acc[i][4] += p[i] * v1.x; acc[i][5] += p[i] * v1.y;
                acc[i][6] += p[i] * v1.z; acc[i][7] += p[i] * v1.w;
            }
        }
        __syncthreads();   // before next tile overwrites Ks/Vs/Ss
    }

    // epilogue: normalize and store
    #pragma unroll
    for (int i = 0; i < 4; i++) {
        const int   r     = ty * 4 + i;
        const float inv_l = 1.f / l_s[r];
        const size_t base = ((size_t)b * SEQ + (q0 + r)) * HDIM;
        float4 o0 = make_float4(acc[i][0] * inv_l, acc[i][1] * inv_l,
                                acc[i][2] * inv_l, acc[i][3] * inv_l);
        float4 o1 = make_float4(acc[i][4] * inv_l, acc[i][5] * inv_l,
                                acc[i][6] * inv_l, acc[i][7] * inv_l);
        *(float4*)&out[base + tx * 4]      = o0;
        *(float4*)&out[base + 64 + tx * 4] = o1;
    }
}

// ======================= launch =============================================
extern "C" void kernel_launch(void* const* d_in, const int* in_sizes, int n_in,
                              void* d_out, int out_size)
{
    const float* x  = (const float*)d_in[0];
    const float* Wq = (const float*)d_in[1];
    const float* Wk = (const float*)d_in[2];
    const float* Wv = (const float*)d_in[3];
    float* out = (float*)d_out;

    static bool attr_set = false;
    if (!attr_set) {
        cudaFuncSetAttribute(attn_kernel,
                             cudaFuncAttributeMaxDynamicSharedMemorySize,
                             SMEM_BYTES);
        attr_set = true;
    }

    // QKV projections: grid.x = 8192/64 row tiles, grid.y selects q/k/v
    dim3 pgrid(BATCH * SEQ / P_BM, 3);
    proj_kernel<<<pgrid, 256>>>(x, Wq, Wk, Wv);

    // attention: grid.x = 2048/64 query tiles, grid.y = batch
    dim3 agrid(SEQ / A_BM, BATCH);
    attn_kernel<<<agrid, 256, SMEM_BYTES>>>(out);
}

// round 5
// speedup vs baseline: 1.9653x; 1.9653x over previous
#include <cuda_runtime.h>
#include <cstdint>
#include <cstddef>

// Problem constants
#define BATCH 4
#define SEQ   2048
#define CDIM  2048
#define HDIM  128

// ---------------- scratch (allocation-free: __device__ globals) -------------
__device__ float g_q[BATCH * SEQ * HDIM];
__device__ float g_k[BATCH * SEQ * HDIM];
__device__ float g_v[BATCH * SEQ * HDIM];

// attention partials (split-KV)
#define AQT    16           // q-tiles per batch (128 rows each)
#define MAXCH  8            // max KV chunks per q-tile
__device__ float g_pacc[BATCH * AQT * MAXCH * 128 * 128];   // 33.5 MB
__device__ float g_pm[BATCH * AQT * MAXCH * 128];
__device__ float g_pl[BATCH * AQT * MAXCH * 128];

// ======================= tf32 mma helpers ===================================
__device__ __forceinline__ uint32_t f2tf32(float f) {
    uint32_t r;
    asm("cvt.rna.tf32.f32 %0, %1;" : "=r"(r) : "f"(f));
    return r;
}
__device__ __forceinline__ void mma_tf32(float* d, const uint32_t* a, const uint32_t* b) {
    asm volatile(
        "mma.sync.aligned.m16n8k8.row.col.f32.tf32.tf32.f32 "
        "{%0,%1,%2,%3}, {%4,%5,%6,%7}, {%8,%9}, {%0,%1,%2,%3};"
        : "+f"(d[0]), "+f"(d[1]), "+f"(d[2]), "+f"(d[3])
        : "r"(a[0]), "r"(a[1]), "r"(a[2]), "r"(a[3]), "r"(b[0]), "r"(b[1]));
}

// ======================= QKV projection (tf32 tensor) =======================
// out[8192,128] = X[8192,2048] @ W[2048,128]. Block: 128x128 tile, BK=32,
// 256 threads = 8 warps (4 m x 2 n), warp tile 32x64, mma m16n8k8 tf32.
#define GAS 36    // As stride (36 % 32 == 4 -> conflict-free frag reads)
#define GBS 132   // Bs stride (132 % 32 == 4)

__global__ __launch_bounds__(256) void proj_kernel(
    const float* __restrict__ x,
    const float* __restrict__ Wq,
    const float* __restrict__ Wk,
    const float* __restrict__ Wv)
{
    const float* W   = (blockIdx.y == 0) ? Wq : (blockIdx.y == 1) ? Wk : Wv;
    float*       out = (blockIdx.y == 0) ? g_q : (blockIdx.y == 1) ? g_k : g_v;

    __shared__ float As[128 * GAS];   // [128][36]
    __shared__ float Bs[32 * GBS];    // [32][132]

    const int tid    = threadIdx.x;
    const int lane   = tid & 31;
    const int wid    = tid >> 5;
    const int warp_m = wid & 3;       // 0..3 -> rows warp_m*32
    const int warp_n = wid >> 2;      // 0..1 -> cols warp_n*64
    const int g      = lane >> 2;     // 0..7
    const int tg     = lane & 3;      // 0..3
    const int row0   = blockIdx.x * 128;

    float d[2][8][4];
    #pragma unroll
    for (int mi = 0; mi < 2; mi++)
        #pragma unroll
        for (int ni = 0; ni < 8; ni++)
            #pragma unroll
            for (int c = 0; c < 4; c++) d[mi][ni][c] = 0.f;

    for (int k0 = 0; k0 < CDIM; k0 += 32) {
        // load A tile 128x32: 1024 float4, 4 per thread
        #pragma unroll
        for (int i = 0; i < 4; i++) {
            const int idx = tid + i * 256;
            const int r   = idx >> 3;
            const int c4  = idx & 7;
            const float4 v = *(const float4*)&x[(size_t)(row0 + r) * CDIM + k0 + c4 * 4];
            *(float4*)&As[r * GAS + c4 * 4] = v;
        }
        // load B tile 32x128: 1024 float4, 4 per thread
        #pragma unroll
        for (int i = 0; i < 4; i++) {
            const int idx = tid + i * 256;
            const int r   = idx >> 5;
            const int c4  = idx & 31;
            const float4 v = *(const float4*)&W[(size_t)(k0 + r) * HDIM + c4 * 4];
            *(float4*)&Bs[r * GBS + c4 * 4] = v;
        }
        __syncthreads();

        #pragma unroll
        for (int ks = 0; ks < 4; ks++) {
            const int kb = ks * 8;
            uint32_t a[2][4], b[8][2];
            #pragma unroll
            for (int mi = 0; mi < 2; mi++) {
                const int rb = warp_m * 32 + mi * 16;
                a[mi][0] = f2tf32(As[(rb + g)     * GAS + kb + tg]);
                a[mi][1] = f2tf32(As[(rb + 8 + g) * GAS + kb + tg]);
                a[mi][2] = f2tf32(As[(rb + g)     * GAS + kb + 4 + tg]);
                a[mi][3] = f2tf32(As[(rb + 8 + g) * GAS + kb + 4 + tg]);
            }
            #pragma unroll
            for (int ni = 0; ni < 8; ni++) {
                const int col = warp_n * 64 + ni * 8 + g;
                b[ni][0] = f2tf32(Bs[(kb + tg)     * GBS + col]);
                b[ni][1] = f2tf32(Bs[(kb + 4 + tg) * GBS + col]);
            }
            #pragma unroll
            for (int mi = 0; mi < 2; mi++)
                #pragma unroll
                for (int ni = 0; ni < 8; ni++)
                    mma_tf32(d[mi][ni], a[mi], b[ni]);
        }
        __syncthreads();
    }

    // epilogue: d fragment -> gmem (float2 per half)
    #pragma unroll
    for (int mi = 0; mi < 2; mi++) {
        #pragma unroll
        for (int ni = 0; ni < 8; ni++) {
            const int row = row0 + warp_m * 32 + mi * 16 + g;
            const int col = warp_n * 64 + ni * 8 + tg * 2;
            *(float2*)&out[(size_t)row * HDIM + col] =
                make_float2(d[mi][ni][0], d[mi][ni][1]);
            *(float2*)&out[(size_t)(row + 8) * HDIM + col] =
                make_float2(d[mi][ni][2], d[mi][ni][3]);
        }
    }
}

// ======================= causal flash attention (split-KV) ==================
// Block = (qt, chunk, batch). BM=128 query rows, BN=64 keys per tile, up to
// CH=4 k-tiles per chunk. 256 threads: S tile 8x4/thread, O tile 8x8/thread.
#define A_BM  128
#define A_BN  64
#define A_CH  4
#define QT_S  132   // Qt [128 kk][128 rows + 4]
#define KT_S  68    // Kt [128 kk][64 cols + 4]
#define VS_S  132   // Vs [64 keys][128 cols + 4]
#define SS_S  68    // Ss [128 rows][64 cols + 4]

#define ASMEM_FLOATS (128 * QT_S + 128 * KT_S + 64 * VS_S + 128 * SS_S + 3 * 128)
#define ASMEM_BYTES  (ASMEM_FLOATS * 4)

__global__ __launch_bounds__(256, 1) void attn_kernel()
{
    const int qt = blockIdx.x;          // 0..15
    const int ci = blockIdx.y;          // 0..7
    const int b  = blockIdx.z;          // 0..3

    const int ntiles = 2 * qt + 2;
    if (ci * A_CH >= ntiles) return;
    const int kt_begin = ci * A_CH;
    const int kt_end   = min(kt_begin + A_CH, ntiles);
    const int q0 = qt * A_BM;

    extern __shared__ float smem[];
    float* Qt      = smem;                       // [128][132] (kk-major)
    float* Kt      = Qt + 128 * QT_S;            // [128][68]  (kk-major)
    float* Vs      = Kt + 128 * KT_S;            // [64][132]
    float* Ss      = Vs + 64 * VS_S;             // [128][68]
    float* m_s     = Ss + 128 * SS_S;            // [128]
    float* l_s     = m_s + 128;
    float* alpha_s = l_s + 128;

    const int tid  = threadIdx.x;
    const int tx   = tid & 15;          // S cols tx*4, O cols tx*8
    const int ty   = tid >> 4;          // rows ty*8..ty*8+7
    const int lane = tid & 31;
    const int warp = tid >> 5;

    const float* Qg = g_q + (size_t)b * SEQ * HDIM;
    const float* Kg = g_k + (size_t)b * SEQ * HDIM;
    const float* Vg = g_v + (size_t)b * SEQ * HDIM;

    // load Q tile transposed: 128x128 -> Qt[kk][row]
    #pragma unroll
    for (int i = 0; i < 16; i++) {
        const int idx = tid + i * 256;
        const int r   = idx >> 5;       // 0..127
        const int c4  = idx & 31;
        const float4 v = *(const float4*)&Qg[(size_t)(q0 + r) * HDIM + c4 * 4];
        Qt[(c4 * 4 + 0) * QT_S + r] = v.x;
        Qt[(c4 * 4 + 1) * QT_S + r] = v.y;
        Qt[(c4 * 4 + 2) * QT_S + r] = v.z;
        Qt[(c4 * 4 + 3) * QT_S + r] = v.w;
    }
    if (tid < 128) { m_s[tid] = -1e30f; l_s[tid] = 0.f; }

    float acc[8][8];
    #pragma unroll
    for (int i = 0; i < 8; i++)
        #pragma unroll
        for (int j = 0; j < 8; j++) acc[i][j] = 0.f;

    const float scale = 0.08838834764831843f;   // 1/sqrt(128)
    __syncthreads();

    for (int kt = kt_begin; kt < kt_end; kt++) {
        const int k0 = kt * A_BN;
        // load K transposed and V straight: 64x128 each
        #pragma unroll
        for (int i = 0; i < 8; i++) {
            const int idx = tid + i * 256;
            const int r   = idx >> 5;   // 0..63
            const int c4  = idx & 31;
            const float4 kv = *(const float4*)&Kg[(size_t)(k0 + r) * HDIM + c4 * 4];
            Kt[(c4 * 4 + 0) * KT_S + r] = kv.x;
            Kt[(c4 * 4 + 1) * KT_S + r] = kv.y;
            Kt[(c4 * 4 + 2) * KT_S + r] = kv.z;
            Kt[(c4 * 4 + 3) * KT_S + r] = kv.w;
            const float4 vv = *(const float4*)&Vg[(size_t)(k0 + r) * HDIM + c4 * 4];
            *(float4*)&Vs[r * VS_S + c4 * 4] = vv;
        }
        __syncthreads();

        // S = Q K^T
        float s[8][4];
        #pragma unroll
        for (int i = 0; i < 8; i++)
            #pragma unroll
            for (int j = 0; j < 4; j++) s[i][j] = 0.f;

        #pragma unroll 4
        for (int kk = 0; kk < HDIM; kk++) {
            const float4 a0 = *(const float4*)&Qt[kk * QT_S + ty * 8];
            const float4 a1 = *(const float4*)&Qt[kk * QT_S + ty * 8 + 4];
            const float4 kb = *(const float4*)&Kt[kk * KT_S + tx * 4];
            float aa[8] = {a0.x, a0.y, a0.z, a0.w, a1.x, a1.y, a1.z, a1.w};
            #pragma unroll
            for (int i = 0; i < 8; i++) {
                s[i][0] += aa[i] * kb.x;
                s[i][1] += aa[i] * kb.y;
                s[i][2] += aa[i] * kb.z;
                s[i][3] += aa[i] * kb.w;
            }
        }

        const bool diag = (k0 + A_BN - 1 > q0);
        #pragma unroll
        for (int i = 0; i < 8; i++) {
            const int qi = q0 + ty * 8 + i;
            float4 o;
            float* op = &o.x;
            #pragma unroll
            for (int j = 0; j < 4; j++) {
                float val = s[i][j] * scale;
                if (diag && (k0 + tx * 4 + j) > qi) val = -1e30f;
                op[j] = val;
            }
            *(float4*)&Ss[(ty * 8 + i) * SS_S + tx * 4] = o;
        }
        __syncthreads();

        // online softmax: each warp owns 16 rows
        #pragma unroll
        for (int rr = 0; rr < 16; rr++) {
            const int row = warp * 16 + rr;
            float x0 = Ss[row * SS_S + lane];
            float x1 = Ss[row * SS_S + 32 + lane];
            float mx = fmaxf(x0, x1);
            #pragma unroll
            for (int off = 16; off > 0; off >>= 1)
                mx = fmaxf(mx, __shfl_xor_sync(0xFFFFFFFFu, mx, off));
            const float m_old = m_s[row];
            const float m_new = fmaxf(m_old, mx);
            const float e0 = __expf(x0 - m_new);
            const float e1 = __expf(x1 - m_new);
            Ss[row * SS_S + lane]      = e0;
            Ss[row * SS_S + 32 + lane] = e1;
            float sum = e0 + e1;
            #pragma unroll
            for (int off = 16; off > 0; off >>= 1)
                sum += __shfl_xor_sync(0xFFFFFFFFu, sum, off);
            if (lane == 0) {
                const float alpha = __expf(m_old - m_new);
                alpha_s[row] = alpha;
                l_s[row]     = l_s[row] * alpha + sum;
                m_s[row]     = m_new;
            }
        }
        __syncthreads();

        // rescale accumulators, then O += P @ V
        #pragma unroll
        for (int i = 0; i < 8; i++) {
            const float al = alpha_s[ty * 8 + i];
            #pragma unroll
            for (int j = 0; j < 8; j++) acc[i][j] *= al;
        }
        for (int kk4 = 0; kk4 < A_BN / 4; kk4++) {
            const int kk = kk4 * 4;
            float p[8][4];
            #pragma unroll
            for (int i = 0; i < 8; i++) {
                const float4 t = *(const float4*)&Ss[(ty * 8 + i) * SS_S + kk];
                p[i][0] = t.x; p[i][1] = t.y; p[i][2] = t.z; p[i][3] = t.w;
            }
            #pragma unroll
            for (int q = 0; q < 4; q++) {
                const float4 v0 = *(const float4*)&Vs[(kk + q) * VS_S + tx * 8];
                const float4 v1 = *(const float4*)&Vs[(kk + q) * VS_S + tx * 8 + 4];
                #pragma unroll
                for (int i = 0; i < 8; i++) {
                    const float pv = p[i][q];
                    acc[i][0] += pv * v0.x; acc[i][1] += pv * v0.y;
                    acc[i][2] += pv * v0.z; acc[i][3] += pv * v0.w;
                    acc[i][4] += pv * v1.x; acc[i][5] += pv * v1.y;
                    acc[i][6] += pv * v1.z; acc[i][7] += pv * v1.w;
                }
            }
        }
        __syncthreads();
    }

    // store partial (unnormalized acc + m + l)
    const int slot = (b * AQT + qt) * MAXCH + ci;
    float* pbase = g_pacc + (size_t)slot * (128 * 128);
    #pragma unroll
    for (int i = 0; i < 8; i++) {
        const int row = ty * 8 + i;
        *(float4*)&pbase[row * 128 + tx * 8] =
            make_float4(acc[i][0], acc[i][1], acc[i][2], acc[i][3]);
        *(float4*)&pbase[row * 128 + tx * 8 + 4] =
            make_float4(acc[i][4], acc[i][5], acc[i][6], acc[i][7]);
    }
    if (tid < 128) {
        g_pm[slot * 128 + tid] = m_s[tid];
        g_pl[slot * 128 + tid] = l_s[tid];
    }
}

// ======================= combine partials ===================================
__global__ __launch_bounds__(256) void combine_kernel(float* __restrict__ out)
{
    const int qt = blockIdx.x;     // 0..15
    const int b  = blockIdx.y;     // 0..3
    const int nch = (2 * qt + 5) >> 2;          // ceil((2qt+2)/4)
    const int slot0 = (b * AQT + qt) * MAXCH;
    const int q0 = qt * A_BM;

    __shared__ float w[MAXCH][128];

    const int tid = threadIdx.x;
    if (tid < 128) {
        const int row = tid;
        float M = -1e30f;
        for (int i = 0; i < nch; i++)
            M = fmaxf(M, g_pm[(slot0 + i) * 128 + row]);
        float L = 0.f;
        for (int i = 0; i < nch; i++)
            L += g_pl[(slot0 + i) * 128 + row] *
                 __expf(g_pm[(slot0 + i) * 128 + row] - M);
        const float invL = 1.f / L;
        for (int i = 0; i < nch; i++)
            w[i][row] = __expf(g_pm[(slot0 + i) * 128 + row] - M) * invL;
    }
    __syncthreads();

    const int c4    = (tid & 31) * 4;
    const int rbase = (tid >> 5) * 16;
    #pragma unroll
    for (int rr = 0; rr < 16; rr++) {
        const int row = rbase + rr;
        float4 o = make_float4(0.f, 0.f, 0.f, 0.f);
        for (int i = 0; i < nch; i++) {
            const float4 pa = *(const float4*)
                &g_pacc[(size_t)(slot0 + i) * (128 * 128) + row * 128 + c4];
            const float wi = w[i][row];
            o.x += wi * pa.x; o.y += wi * pa.y;
            o.z += wi * pa.z; o.w += wi * pa.w;
        }
        *(float4*)&out[((size_t)b * SEQ + q0 + row) * HDIM + c4] = o;
    }
}

// ======================= launch =============================================
extern "C" void kernel_launch(void* const* d_in, const int* in_sizes, int n_in,
                              void* d_out, int out_size)
{
    const float* x  = (const float*)d_in[0];
    const float* Wq = (const float*)d_in[1];
    const float* Wk = (const float*)d_in[2];
    const float* Wv = (const float*)d_in[3];
    float* out = (float*)d_out;

    static bool attr_set = false;
    if (!attr_set) {
        cudaFuncSetAttribute(attn_kernel,
                             cudaFuncAttributeMaxDynamicSharedMemorySize,
                             ASMEM_BYTES);
        attr_set = true;
    }

    // QKV projections (tf32 tensor): 64 M-tiles x 3 weights
    dim3 pgrid(BATCH * SEQ / 128, 3);
    proj_kernel<<<pgrid, 256>>>(x, Wq, Wk, Wv);

    // attention chunks: (qt, chunk, batch); inactive chunks exit immediately
    dim3 agrid(AQT, MAXCH, BATCH);
    attn_kernel<<<agrid, 256, ASMEM_BYTES>>>();

    // combine
    dim3 cgrid(AQT, BATCH);
    combine_kernel<<<cgrid, 256>>>(out);
}

// round 7
// speedup vs baseline: 3.0700x; 1.5621x over previous
#include <cuda_runtime.h>
#include <cstdint>
#include <cstddef>

// Problem constants
#define BATCH 4
#define SEQ   2048
#define CDIM  2048
#define HDIM  128

// ---------------- scratch (allocation-free: __device__ globals) -------------
__device__ float g_q[BATCH * SEQ * HDIM];
__device__ float g_k[BATCH * SEQ * HDIM];
__device__ float g_v[BATCH * SEQ * HDIM];

// attention partials (split-KV)
#define AQT    16           // q-tiles per batch (128 rows each)
#define MAXCH  8            // max KV chunks per q-tile
__device__ float g_pacc[BATCH * AQT * MAXCH * 128 * 128];   // 33.5 MB
__device__ float g_pm[BATCH * AQT * MAXCH * 128];
__device__ float g_pl[BATCH * AQT * MAXCH * 128];

// ======================= tf32 mma helpers ===================================
__device__ __forceinline__ uint32_t f2tf32(float f) {
    uint32_t r;
    asm("cvt.rna.tf32.f32 %0, %1;" : "=r"(r) : "f"(f));
    return r;
}
__device__ __forceinline__ float tf32f(float f) {   // tf32 bits kept in a float slot
    return __uint_as_float(f2tf32(f));
}
__device__ __forceinline__ void mma_tf32(float* d, const uint32_t* a, const uint32_t* b) {
    asm volatile(
        "mma.sync.aligned.m16n8k8.row.col.f32.tf32.tf32.f32 "
        "{%0,%1,%2,%3}, {%4,%5,%6,%7}, {%8,%9}, {%0,%1,%2,%3};"
        : "+f"(d[0]), "+f"(d[1]), "+f"(d[2]), "+f"(d[3])
        : "r"(a[0]), "r"(a[1]), "r"(a[2]), "r"(a[3]), "r"(b[0]), "r"(b[1]));
}

// ======================= QKV projection (tf32 tensor) =======================
// out[8192,128] = X[8192,2048] @ W[2048,128]. Block: 64x128 tile, BK=32,
// 256 threads = 8 warps (2 m x 4 n), warp tile 32x32. tf32 converted at
// smem-store time; inner loop = raw LDS + MMA.
#define GAS 36    // As stride (36 % 32 == 4 -> conflict-free frag reads)
#define GBS 132   // Bs stride (132 % 32 == 4)

__global__ __launch_bounds__(256) void proj_kernel(
    const float* __restrict__ x,
    const float* __restrict__ Wq,
    const float* __restrict__ Wk,
    const float* __restrict__ Wv)
{
    const float* W   = (blockIdx.y == 0) ? Wq : (blockIdx.y == 1) ? Wk : Wv;
    float*       out = (blockIdx.y == 0) ? g_q : (blockIdx.y == 1) ? g_k : g_v;

    __shared__ float As[64 * GAS];    // [64][36]  tf32 bits
    __shared__ float Bs[32 * GBS];    // [32][132] tf32 bits

    const int tid    = threadIdx.x;
    const int lane   = tid & 31;
    const int wid    = tid >> 5;
    const int warp_m = wid & 1;       // rows warp_m*32
    const int warp_n = wid >> 1;      // cols warp_n*32
    const int g      = lane >> 2;     // 0..7
    const int tg     = lane & 3;      // 0..3
    const int row0   = blockIdx.x * 64;

    float d[2][4][4];
    #pragma unroll
    for (int mi = 0; mi < 2; mi++)
        #pragma unroll
        for (int ni = 0; ni < 4; ni++)
            #pragma unroll
            for (int c = 0; c < 4; c++) d[mi][ni][c] = 0.f;

    for (int k0 = 0; k0 < CDIM; k0 += 32) {
        // A tile 64x32: 512 float4, 2 per thread; cvt to tf32 at store
        #pragma unroll
        for (int i = 0; i < 2; i++) {
            const int idx = tid + i * 256;
            const int r   = idx >> 3;       // 0..63
            const int c4  = idx & 7;        // 0..7
            const float4 v = *(const float4*)&x[(size_t)(row0 + r) * CDIM + k0 + c4 * 4];
            float* dst = &As[r * GAS + c4 * 4];
            dst[0] = tf32f(v.x); dst[1] = tf32f(v.y);
            dst[2] = tf32f(v.z); dst[3] = tf32f(v.w);
        }
        // B tile 32x128: 1024 float4, 4 per thread
        #pragma unroll
        for (int i = 0; i < 4; i++) {
            const int idx = tid + i * 256;
            const int r   = idx >> 5;       // 0..31
            const int c4  = idx & 31;
            const float4 v = *(const float4*)&W[(size_t)(k0 + r) * HDIM + c4 * 4];
            float* dst = &Bs[r * GBS + c4 * 4];
            dst[0] = tf32f(v.x); dst[1] = tf32f(v.y);
            dst[2] = tf32f(v.z); dst[3] = tf32f(v.w);
        }
        __syncthreads();

        #pragma unroll
        for (int ks = 0; ks < 4; ks++) {
            const int kb = ks * 8;
            uint32_t a[2][4], b[4][2];
            #pragma unroll
            for (int mi = 0; mi < 2; mi++) {
                const int rb = warp_m * 32 + mi * 16;
                a[mi][0] = __float_as_uint(As[(rb + g)     * GAS + kb + tg]);
                a[mi][1] = __float_as_uint(As[(rb + 8 + g) * GAS + kb + tg]);
                a[mi][2] = __float_as_uint(As[(rb + g)     * GAS + kb + 4 + tg]);
                a[mi][3] = __float_as_uint(As[(rb + 8 + g) * GAS + kb + 4 + tg]);
            }
            #pragma unroll
            for (int ni = 0; ni < 4; ni++) {
                const int col = warp_n * 32 + ni * 8 + g;
                b[ni][0] = __float_as_uint(Bs[(kb + tg)     * GBS + col]);
                b[ni][1] = __float_as_uint(Bs[(kb + 4 + tg) * GBS + col]);
            }
            #pragma unroll
            for (int mi = 0; mi < 2; mi++)
                #pragma unroll
                for (int ni = 0; ni < 4; ni++)
                    mma_tf32(d[mi][ni], a[mi], b[ni]);
        }
        __syncthreads();
    }

    #pragma unroll
    for (int mi = 0; mi < 2; mi++) {
        #pragma unroll
        for (int ni = 0; ni < 4; ni++) {
            const int row = row0 + warp_m * 32 + mi * 16 + g;
            const int col = warp_n * 32 + ni * 8 + tg * 2;
            *(float2*)&out[(size_t)row * HDIM + col] =
                make_float2(d[mi][ni][0], d[mi][ni][1]);
            *(float2*)&out[(size_t)(row + 8) * HDIM + col] =
                make_float2(d[mi][ni][2], d[mi][ni][3]);
        }
    }
}

// ======================= causal flash attention (split-KV, tf32 mma) ========
// Block = (qt, chunk, batch). BM=128 rows, BN=64 keys/tile, up to 4 tiles.
// 256 threads = 8 warps. S mma: warps 4m x 2n (32x32 warp tile).
// PV mma: warps 4m x 2n over hdim (32x64 warp tile).
#define A_BM  128
#define A_BN  64
#define A_CH  4
#define QS_S  132   // Qs [128 rows][128 + 4]   tf32 bits, scale folded
#define KS_S  132   // Ks [64 keys][128 + 4]    tf32 bits
#define VS_S  136   // Vs [64 keys][128 + 8]    tf32 bits
#define SS_S  68    // Ss [128 rows][64 + 4]    fp32 scores -> tf32 exp bits

#define ASMEM_FLOATS (128 * QS_S + 64 * KS_S + 64 * VS_S + 128 * SS_S + 3 * 128)
#define ASMEM_BYTES  (ASMEM_FLOATS * 4)

__global__ __launch_bounds__(256, 1) void attn_kernel()
{
    const int qt = blockIdx.x;          // 0..15
    const int ci = blockIdx.y;          // 0..7
    const int b  = blockIdx.z;          // 0..3

    const int ntiles = 2 * qt + 2;
    if (ci * A_CH >= ntiles) return;
    const int kt_begin = ci * A_CH;
    const int kt_end   = min(kt_begin + A_CH, ntiles);
    const int q0 = qt * A_BM;

    extern __shared__ float smem[];
    float* Qs      = smem;                       // [128][132]
    float* Ks      = Qs + 128 * QS_S;            // [64][132]
    float* Vs      = Ks + 64 * KS_S;             // [64][136]
    float* Ss      = Vs + 64 * VS_S;             // [128][68]
    float* m_s     = Ss + 128 * SS_S;            // [128]
    float* l_s     = m_s + 128;
    float* alpha_s = l_s + 128;

    const int tid    = threadIdx.x;
    const int lane   = tid & 31;
    const int wid    = tid >> 5;
    const int warp_m = wid & 3;         // rows warp_m*32 (both matmuls)
    const int warp_n = wid >> 2;        // S: key cols warp_n*32; PV: hdim warp_n*64
    const int g      = lane >> 2;       // 0..7
    const int tg     = lane & 3;        // 0..3

    const float* Qg = g_q + (size_t)b * SEQ * HDIM;
    const float* Kg = g_k + (size_t)b * SEQ * HDIM;
    const float* Vg = g_v + (size_t)b * SEQ * HDIM;

    const float scale = 0.08838834764831843f;   // 1/sqrt(128), folded into Q

    // load Q tile (128x128), fold scale, cvt to tf32
    #pragma unroll
    for (int i = 0; i < 16; i++) {
        const int idx = tid + i * 256;
        const int r   = idx >> 5;
        const int c4  = idx & 31;
        const float4 v = *(const float4*)&Qg[(size_t)(q0 + r) * HDIM + c4 * 4];
        float* dst = &Qs[r * QS_S + c4 * 4];
        dst[0] = tf32f(v.x * scale); dst[1] = tf32f(v.y * scale);
        dst[2] = tf32f(v.z * scale); dst[3] = tf32f(v.w * scale);
    }
    if (tid < 128) { m_s[tid] = -1e30f; l_s[tid] = 0.f; }

    float o[2][8][4];
    #pragma unroll
    for (int mi = 0; mi < 2; mi++)
        #pragma unroll
        for (int ni = 0; ni < 8; ni++)
            #pragma unroll
            for (int c = 0; c < 4; c++) o[mi][ni][c] = 0.f;

    __syncthreads();

    for (int kt = kt_begin; kt < kt_end; kt++) {
        const int k0 = kt * A_BN;
        // stage K and V (64x128 each), tf32-converted
        #pragma unroll
        for (int i = 0; i < 8; i++) {
            const int idx = tid + i * 256;
            const int r   = idx >> 5;   // 0..63
            const int c4  = idx & 31;
            const float4 kv = *(const float4*)&Kg[(size_t)(k0 + r) * HDIM + c4 * 4];
            float* kd = &Ks[r * KS_S + c4 * 4];
            kd[0] = tf32f(kv.x); kd[1] = tf32f(kv.y);
            kd[2] = tf32f(kv.z); kd[3] = tf32f(kv.w);
            const float4 vv = *(const float4*)&Vg[(size_t)(k0 + r) * HDIM + c4 * 4];
            float* vd = &Vs[r * VS_S + c4 * 4];
            vd[0] = tf32f(vv.x); vd[1] = tf32f(vv.y);
            vd[2] = tf32f(vv.z); vd[3] = tf32f(vv.w);
        }
        __syncthreads();

        // ---- S = Q K^T via tf32 mma: warp tile 32 rows x 32 keys ----
        float s[2][4][4];
        #pragma unroll
        for (int mi = 0; mi < 2; mi++)
            #pragma unroll
            for (int ni = 0; ni < 4; ni++)
                #pragma unroll
                for (int c = 0; c < 4; c++) s[mi][ni][c] = 0.f;

        #pragma unroll
        for (int ks = 0; ks < 16; ks++) {
            const int kb = ks * 8;
            uint32_t a[2][4], kbf[4][2];
            #pragma unroll
            for (int mi = 0; mi < 2; mi++) {
                const int rb = warp_m * 32 + mi * 16;
                a[mi][0] = __float_as_uint(Qs[(rb + g)     * QS_S + kb + tg]);
                a[mi][1] = __float_as_uint(Qs[(rb + 8 + g) * QS_S + kb + tg]);
                a[mi][2] = __float_as_uint(Qs[(rb + g)     * QS_S + kb + 4 + tg]);
                a[mi][3] = __float_as_uint(Qs[(rb + 8 + g) * QS_S + kb + 4 + tg]);
            }
            #pragma unroll
            for (int ni = 0; ni < 4; ni++) {
                const int key = warp_n * 32 + ni * 8 + g;
                kbf[ni][0] = __float_as_uint(Ks[key * KS_S + kb + tg]);
                kbf[ni][1] = __float_as_uint(Ks[key * KS_S + kb + 4 + tg]);
            }
            #pragma unroll
            for (int mi = 0; mi < 2; mi++)
                #pragma unroll
                for (int ni = 0; ni < 4; ni++)
                    mma_tf32(s[mi][ni], a[mi], kbf[ni]);
        }

        // mask + store S to smem (fp32)
        const bool diag = (k0 + A_BN - 1 > q0);
        #pragma unroll
        for (int mi = 0; mi < 2; mi++) {
            #pragma unroll
            for (int ni = 0; ni < 4; ni++) {
                const int r0  = warp_m * 32 + mi * 16 + g;
                const int col = warp_n * 32 + ni * 8 + tg * 2;
                float c0 = s[mi][ni][0], c1 = s[mi][ni][1];
                float c2 = s[mi][ni][2], c3 = s[mi][ni][3];
                if (diag) {
                    const int kc = k0 + col, qa = q0 + r0, qb = qa + 8;
                    if (kc     > qa) c0 = -1e30f;
                    if (kc + 1 > qa) c1 = -1e30f;
                    if (kc     > qb) c2 = -1e30f;
                    if (kc + 1 > qb) c3 = -1e30f;
                }
                *(float2*)&Ss[r0 * SS_S + col]       = make_float2(c0, c1);
                *(float2*)&Ss[(r0 + 8) * SS_S + col] = make_float2(c2, c3);
            }
        }
        __syncthreads();

        // ---- online softmax: each warp owns 16 rows; exp stored as tf32 ----
        #pragma unroll
        for (int rr = 0; rr < 16; rr++) {
            const int row = wid * 16 + rr;
            float x0 = Ss[row * SS_S + lane];
            float x1 = Ss[row * SS_S + 32 + lane];
            float mx = fmaxf(x0, x1);
            #pragma unroll
            for (int off = 16; off > 0; off >>= 1)
                mx = fmaxf(mx, __shfl_xor_sync(0xFFFFFFFFu, mx, off));
            const float m_old = m_s[row];
            const float m_new = fmaxf(m_old, mx);
            const float e0 = __expf(x0 - m_new);
            const float e1 = __expf(x1 - m_new);
            Ss[row * SS_S + lane]      = __uint_as_float(f2tf32(e0));
            Ss[row * SS_S + 32 + lane] = __uint_as_float(f2tf32(e1));
            float sum = e0 + e1;
            #pragma unroll
            for (int off = 16; off > 0; off >>= 1)
                sum += __shfl_xor_sync(0xFFFFFFFFu, sum, off);
            if (lane == 0) {
                const float alpha = __expf(m_old - m_new);
                alpha_s[row] = alpha;
                l_s[row]     = l_s[row] * alpha + sum;
                m_s[row]     = m_new;
            }
        }
        __syncthreads();

        // ---- rescale O, then O += P V via tf32 mma (warp tile 32x64) ----
        #pragma unroll
        for (int mi = 0; mi < 2; mi++) {
            const float al0 = alpha_s[warp_m * 32 + mi * 16 + g];
            const float al1 = alpha_s[warp_m * 32 + mi * 16 + 8 + g];
            #pragma unroll
            for (int ni = 0; ni < 8; ni++) {
                o[mi][ni][0] *= al0; o[mi][ni][1] *= al0;
                o[mi][ni][2] *= al1; o[mi][ni][3] *= al1;
            }
        }
        #pragma unroll
        for (int ks = 0; ks < 8; ks++) {
            const int kb = ks * 8;
            uint32_t a[2][4], vb[8][2];
            #pragma unroll
            for (int mi = 0; mi < 2; mi++) {
                const int rb = warp_m * 32 + mi * 16;
                a[mi][0] = __float_as_uint(Ss[(rb + g)     * SS_S + kb + tg]);
                a[mi][1] = __float_as_uint(Ss[(rb + 8 + g) * SS_S + kb + tg]);
                a[mi][2] = __float_as_uint(Ss[(rb + g)     * SS_S + kb + 4 + tg]);
                a[mi][3] = __float_as_uint(Ss[(rb + 8 + g) * SS_S + kb + 4 + tg]);
            }
            #pragma unroll
            for (int ni = 0; ni < 8; ni++) {
                const int col = warp_n * 64 + ni * 8 + g;
                vb[ni][0] = __float_as_uint(Vs[(kb + tg)     * VS_S + col]);
                vb[ni][1] = __float_as_uint(Vs[(kb + 4 + tg) * VS_S + col]);
            }
            #pragma unroll
            for (int mi = 0; mi < 2; mi++)
                #pragma unroll
                for (int ni = 0; ni < 8; ni++)
                    mma_tf32(o[mi][ni], a[mi], vb[ni]);
        }
        __syncthreads();   // before next tile overwrites Ks/Vs/Ss
    }

    // store partial (unnormalized O + m + l)
    const int slot = (b * AQT + qt) * MAXCH + ci;
    float* pbase = g_pacc + (size_t)slot * (128 * 128);
    #pragma unroll
    for (int mi = 0; mi < 2; mi++) {
        #pragma unroll
        for (int ni = 0; ni < 8; ni++) {
            const int row = warp_m * 32 + mi * 16 + g;
            const int col = warp_n * 64 + ni * 8 + tg * 2;
            *(float2*)&pbase[row * 128 + col] =
                make_float2(o[mi][ni][0], o[mi][ni][1]);
            *(float2*)&pbase[(row + 8) * 128 + col] =
                make_float2(o[mi][ni][2], o[mi][ni][3]);
        }
    }
    if (tid < 128) {
        g_pm[slot * 128 + tid] = m_s[tid];
        g_pl[slot * 128 + tid] = l_s[tid];
    }
}

// ======================= combine partials ===================================
__global__ __launch_bounds__(256) void combine_kernel(float* __restrict__ out)
{
    const int qt = blockIdx.x;     // 0..15
    const int b  = blockIdx.y;     // 0..3
    const int nch = (2 * qt + 5) >> 2;          // ceil((2qt+2)/4)
    const int slot0 = (b * AQT + qt) * MAXCH;
    const int q0 = qt * A_BM;

    __shared__ float w[MAXCH][128];

    const int tid = threadIdx.x;
    if (tid < 128) {
        const int row = tid;
        float M = -1e30f;
        for (int i = 0; i < nch; i++)
            M = fmaxf(M, g_pm[(slot0 + i) * 128 + row]);
        float L = 0.f;
        for (int i = 0; i < nch; i++)
            L += g_pl[(slot0 + i) * 128 + row] *
                 __expf(g_pm[(slot0 + i) * 128 + row] - M);
        const float invL = 1.f / L;
        for (int i = 0; i < nch; i++)
            w[i][row] = __expf(g_pm[(slot0 + i) * 128 + row] - M) * invL;
    }
    __syncthreads();

    const int c4    = (tid & 31) * 4;
    const int rbase = (tid >> 5) * 16;
    #pragma unroll
    for (int rr = 0; rr < 16; rr++) {
        const int row = rbase + rr;
        float4 o = make_float4(0.f, 0.f, 0.f, 0.f);
        for (int i = 0; i < nch; i++) {
            const float4 pa = *(const float4*)
                &g_pacc[(size_t)(slot0 + i) * (128 * 128) + row * 128 + c4];
            const float wi = w[i][row];
            o.x += wi * pa.x; o.y += wi * pa.y;
            o.z += wi * pa.z; o.w += wi * pa.w;
        }
        *(float4*)&out[((size_t)b * SEQ + q0 + row) * HDIM + c4] = o;
    }
}

// ======================= launch =============================================
extern "C" void kernel_launch(void* const* d_in, const int* in_sizes, int n_in,
                              void* d_out, int out_size)
{
    const float* x  = (const float*)d_in[0];
    const float* Wq = (const float*)d_in[1];
    const float* Wk = (const float*)d_in[2];
    const float* Wv = (const float*)d_in[3];
    float* out = (float*)d_out;

    static bool attr_set = false;
    if (!attr_set) {
        cudaFuncSetAttribute(attn_kernel,
                             cudaFuncAttributeMaxDynamicSharedMemorySize,
                             ASMEM_BYTES);
        attr_set = true;
    }

    // QKV projections (tf32 tensor): 128 M-tiles x 3 weights = 384 CTAs
    dim3 pgrid(BATCH * SEQ / 64, 3);
    proj_kernel<<<pgrid, 256>>>(x, Wq, Wk, Wv);

    // attention chunks: (qt, chunk, batch); inactive chunks exit immediately
    dim3 agrid(AQT, MAXCH, BATCH);
    attn_kernel<<<agrid, 256, ASMEM_BYTES>>>();

    // combine
    dim3 cgrid(AQT, BATCH);
    combine_kernel<<<cgrid, 256>>>(out);
}

// round 10
// speedup vs baseline: 3.0920x; 1.0072x over previous
#include <cuda_runtime.h>
#include <cstdint>
#include <cstddef>

// Problem constants
#define BATCH 4
#define SEQ   2048
#define CDIM  2048
#define HDIM  128

// ---------------- scratch (allocation-free: __device__ globals) -------------
__device__ float g_q[BATCH * SEQ * HDIM];
__device__ float g_k[BATCH * SEQ * HDIM];
__device__ float g_v[BATCH * SEQ * HDIM];

// attention partials (split-KV)
#define AQT    16           // q-tiles per batch (128 rows each)
#define MAXCH  8            // max KV chunks per q-tile
__device__ float g_pacc[BATCH * AQT * MAXCH * 128 * 128];   // 33.5 MB
__device__ float g_pm[BATCH * AQT * MAXCH * 128];
__device__ float g_pl[BATCH * AQT * MAXCH * 128];

// ======================= tf32 mma helpers ===================================
__device__ __forceinline__ uint32_t f2tf32(float f) {
    uint32_t r;
    asm("cvt.rna.tf32.f32 %0, %1;" : "=r"(r) : "f"(f));
    return r;
}
__device__ __forceinline__ float tf32f(float f) {   // tf32 bits kept in a float slot
    return __uint_as_float(f2tf32(f));
}
__device__ __forceinline__ void mma_tf32(float* d, const uint32_t* a, const uint32_t* b) {
    asm volatile(
        "mma.sync.aligned.m16n8k8.row.col.f32.tf32.tf32.f32 "
        "{%0,%1,%2,%3}, {%4,%5,%6,%7}, {%8,%9}, {%0,%1,%2,%3};"
        : "+f"(d[0]), "+f"(d[1]), "+f"(d[2]), "+f"(d[3])
        : "r"(a[0]), "r"(a[1]), "r"(a[2]), "r"(a[3]), "r"(b[0]), "r"(b[1]));
}

// ======================= QKV projection (tf32, fragment-ready smem) =========
// out[8192,128] = X[8192,2048] @ W[2048,128]. Block: 64x128 tile, BK=32,
// 256 threads = 8 warps (2m x 4n), warp tile 32x32.
// Smem holds mma fragments directly: A-frag load = LDS.128, B-frag = LDS.64.
// Gmem tile k+1 prefetched into registers during MMAs of tile k.
//
// Afrag: 16 tiles (m16 0..3 x ks 0..3), each 132 floats: lane*4 + slot
//        slot = half8 + 2*tghalf  (a0,a1,a2,a3 of m16n8k8 row-major A frag)
// Bfrag: 64 tiles (ks 0..3 x ni 0..15), each 66 floats: lane*2 + slot
//        slot 0 -> b0 (k=kb+tg), slot 1 -> b1 (k=kb+4+tg)
#define AF_TS 132
#define BF_TS 66

__global__ __launch_bounds__(256) void proj_kernel(
    const float* __restrict__ x,
    const float* __restrict__ Wq,
    const float* __restrict__ Wk,
    const float* __restrict__ Wv)
{
    const float* W   = (blockIdx.y == 0) ? Wq : (blockIdx.y == 1) ? Wk : Wv;
    float*       out = (blockIdx.y == 0) ? g_q : (blockIdx.y == 1) ? g_k : g_v;

    __shared__ __align__(16) float Afrag[16 * AF_TS];   // 8.25 KB
    __shared__ __align__(16) float Bfrag[64 * BF_TS];   // 16.5 KB

    const int tid    = threadIdx.x;
    const int lane   = tid & 31;
    const int wid    = tid >> 5;
    const int warp_m = wid & 1;       // rows warp_m*32
    const int warp_n = wid >> 1;      // cols warp_n*32
    const int row0   = blockIdx.x * 64;

    // ---- A loader precompute (2 float4/thread: rows ar0, ar0+32) ----
    const int ar0   = tid >> 3;                 // 0..31
    const int ac0   = (tid & 7) * 4;            // 0..28
    const int aks   = ac0 >> 3;
    const int aslb  = ((ac0 & 7) >> 2) * 2;     // 2*tghalf
    float* adst[2];
    const float* asrc[2];
    #pragma unroll
    for (int i = 0; i < 2; i++) {
        const int r     = ar0 + 32 * i;
        const int m16   = r >> 4;
        const int half8 = (r >> 3) & 1;
        const int g     = r & 7;
        adst[i] = &Afrag[(m16 * 4 + aks) * AF_TS + g * 16 + half8 + aslb];
        asrc[i] = &x[(size_t)(row0 + r) * CDIM + ac0];
    }

    // ---- B loader precompute (4 float4/thread) ----
    const int br0 = tid >> 5;                   // 0..7
    const int bc0 = (tid & 31) * 4;             // 0..124
    const int bni = bc0 >> 3;
    const int bg  = bc0 & 7;                    // 0 or 4
    float* bdst[4];
    const float* bsrc[4];
    #pragma unroll
    for (int i = 0; i < 4; i++) {
        const int r     = br0 + 8 * i;          // 0..31
        const int bks   = r >> 3;
        const int rr    = r & 7;
        const int bslot = rr >> 2;
        const int btg   = rr & 3;
        bdst[i] = &Bfrag[(bks * 16 + bni) * BF_TS + bg * 8 + btg * 2 + bslot];
        bsrc[i] = &W[(size_t)r * HDIM + bc0];
    }

    float d[2][4][4];
    #pragma unroll
    for (int mi = 0; mi < 2; mi++)
        #pragma unroll
        for (int ni = 0; ni < 4; ni++)
            #pragma unroll
            for (int c = 0; c < 4; c++) d[mi][ni][c] = 0.f;

    // initial prefetch (k-tile 0)
    float4 areg[2], breg[4];
    #pragma unroll
    for (int i = 0; i < 2; i++) areg[i] = *(const float4*)asrc[i];
    #pragma unroll
    for (int i = 0; i < 4; i++) breg[i] = *(const float4*)bsrc[i];

    for (int kb = 0; kb < CDIM / 32; kb++) {
        // store current tile (cvt to tf32 at store; scatter to fragment slots)
        #pragma unroll
        for (int i = 0; i < 2; i++) {
            adst[i][0]  = tf32f(areg[i].x);
            adst[i][4]  = tf32f(areg[i].y);
            adst[i][8]  = tf32f(areg[i].z);
            adst[i][12] = tf32f(areg[i].w);
        }
        #pragma unroll
        for (int i = 0; i < 4; i++) {
            bdst[i][0]  = tf32f(breg[i].x);
            bdst[i][8]  = tf32f(breg[i].y);
            bdst[i][16] = tf32f(breg[i].z);
            bdst[i][24] = tf32f(breg[i].w);
        }
        __syncthreads();

        // prefetch next k-tile into registers (in flight during MMAs)
        if (kb + 1 < CDIM / 32) {
            #pragma unroll
            for (int i = 0; i < 2; i++)
                areg[i] = *(const float4*)(asrc[i] + (kb + 1) * 32);
            #pragma unroll
            for (int i = 0; i < 4; i++)
                breg[i] = *(const float4*)(bsrc[i] + (size_t)(kb + 1) * 32 * HDIM);
        }

        // MMAs: fragment loads are LDS.128 (A) / LDS.64 (B)
        #pragma unroll
        for (int ks = 0; ks < 4; ks++) {
            uint32_t a[2][4], b[4][2];
            #pragma unroll
            for (int mi = 0; mi < 2; mi++) {
                const float4 va = *(const float4*)
                    &Afrag[((warp_m * 2 + mi) * 4 + ks) * AF_TS + lane * 4];
                a[mi][0] = __float_as_uint(va.x);
                a[mi][1] = __float_as_uint(va.y);
                a[mi][2] = __float_as_uint(va.z);
                a[mi][3] = __float_as_uint(va.w);
            }
            #pragma unroll
            for (int ni = 0; ni < 4; ni++) {
                const float2 vb = *(const float2*)
                    &Bfrag[(ks * 16 + warp_n * 4 + ni) * BF_TS + lane * 2];
                b[ni][0] = __float_as_uint(vb.x);
                b[ni][1] = __float_as_uint(vb.y);
            }
            #pragma unroll
            for (int mi = 0; mi < 2; mi++)
                #pragma unroll
                for (int ni = 0; ni < 4; ni++)
                    mma_tf32(d[mi][ni], a[mi], b[ni]);
        }
        __syncthreads();
    }

    // epilogue
    const int g  = lane >> 2;
    const int tg = lane & 3;
    #pragma unroll
    for (int mi = 0; mi < 2; mi++) {
        #pragma unroll
        for (int ni = 0; ni < 4; ni++) {
            const int row = row0 + warp_m * 32 + mi * 16 + g;
            const int col = warp_n * 32 + ni * 8 + tg * 2;
            *(float2*)&out[(size_t)row * HDIM + col] =
                make_float2(d[mi][ni][0], d[mi][ni][1]);
            *(float2*)&out[(size_t)(row + 8) * HDIM + col] =
                make_float2(d[mi][ni][2], d[mi][ni][3]);
        }
    }
}

// ======================= causal flash attention (split-KV, tf32 mma) ========
// Block = (qt, chunk, batch). BM=128 rows, BN=64 keys/tile, up to 4 tiles.
// 256 threads = 8 warps. S mma: warps 4m x 2n (32x32 warp tile).
// PV mma: warps 4m x 2n over hdim (32x64 warp tile).
#define A_BM  128
#define A_BN  64
#define A_CH  4
#define QS_S  132   // Qs [128 rows][128 + 4]   tf32 bits, scale folded
#define KS_S  132   // Ks [64 keys][128 + 4]    tf32 bits
#define VS_S  136   // Vs [64 keys][128 + 8]    tf32 bits
#define SS_S  68    // Ss [128 rows][64 + 4]    fp32 scores -> tf32 exp bits

#define ASMEM_FLOATS (128 * QS_S + 64 * KS_S + 64 * VS_S + 128 * SS_S + 3 * 128)
#define ASMEM_BYTES  (ASMEM_FLOATS * 4)

__global__ __launch_bounds__(256, 1) void attn_kernel()
{
    const int qt = blockIdx.x;          // 0..15
    const int ci = blockIdx.y;          // 0..7
    const int b  = blockIdx.z;          // 0..3

    const int ntiles = 2 * qt + 2;
    if (ci * A_CH >= ntiles) return;
    const int kt_begin = ci * A_CH;
    const int kt_end   = min(kt_begin + A_CH, ntiles);
    const int q0 = qt * A_BM;

    extern __shared__ float smem[];
    float* Qs      = smem;                       // [128][132]
    float* Ks      = Qs + 128 * QS_S;            // [64][132]
    float* Vs      = Ks + 64 * KS_S;             // [64][136]
    float* Ss      = Vs + 64 * VS_S;             // [128][68]
    float* m_s     = Ss + 128 * SS_S;            // [128]
    float* l_s     = m_s + 128;
    float* alpha_s = l_s + 128;

    const int tid    = threadIdx.x;
    const int lane   = tid & 31;
    const int wid    = tid >> 5;
    const int warp_m = wid & 3;         // rows warp_m*32 (both matmuls)
    const int warp_n = wid >> 2;        // S: key cols warp_n*32; PV: hdim warp_n*64
    const int g      = lane >> 2;       // 0..7
    const int tg     = lane & 3;        // 0..3

    const float* Qg = g_q + (size_t)b * SEQ * HDIM;
    const float* Kg = g_k + (size_t)b * SEQ * HDIM;
    const float* Vg = g_v + (size_t)b * SEQ * HDIM;

    const float scale = 0.08838834764831843f;   // 1/sqrt(128), folded into Q

    // load Q tile (128x128), fold scale, cvt to tf32
    #pragma unroll
    for (int i = 0; i < 16; i++) {
        const int idx = tid + i * 256;
        const int r   = idx >> 5;
        const int c4  = idx & 31;
        const float4 v = *(const float4*)&Qg[(size_t)(q0 + r) * HDIM + c4 * 4];
        float* dst = &Qs[r * QS_S + c4 * 4];
        dst[0] = tf32f(v.x * scale); dst[1] = tf32f(v.y * scale);
        dst[2] = tf32f(v.z * scale); dst[3] = tf32f(v.w * scale);
    }
    if (tid < 128) { m_s[tid] = -1e30f; l_s[tid] = 0.f; }

    float o[2][8][4];
    #pragma unroll
    for (int mi = 0; mi < 2; mi++)
        #pragma unroll
        for (int ni = 0; ni < 8; ni++)
            #pragma unroll
            for (int c = 0; c < 4; c++) o[mi][ni][c] = 0.f;

    __syncthreads();

    for (int kt = kt_begin; kt < kt_end; kt++) {
        const int k0 = kt * A_BN;
        // stage K and V (64x128 each), tf32-converted
        #pragma unroll
        for (int i = 0; i < 8; i++) {
            const int idx = tid + i * 256;
            const int r   = idx >> 5;   // 0..63
            const int c4  = idx & 31;
            const float4 kv = *(const float4*)&Kg[(size_t)(k0 + r) * HDIM + c4 * 4];
            float* kd = &Ks[r * KS_S + c4 * 4];
            kd[0] = tf32f(kv.x); kd[1] = tf32f(kv.y);
            kd[2] = tf32f(kv.z); kd[3] = tf32f(kv.w);
            const float4 vv = *(const float4*)&Vg[(size_t)(k0 + r) * HDIM + c4 * 4];
            float* vd = &Vs[r * VS_S + c4 * 4];
            vd[0] = tf32f(vv.x); vd[1] = tf32f(vv.y);
            vd[2] = tf32f(vv.z); vd[3] = tf32f(vv.w);
        }
        __syncthreads();

        // ---- S = Q K^T via tf32 mma: warp tile 32 rows x 32 keys ----
        float s[2][4][4];
        #pragma unroll
        for (int mi = 0; mi < 2; mi++)
            #pragma unroll
            for (int ni = 0; ni < 4; ni++)
                #pragma unroll
                for (int c = 0; c < 4; c++) s[mi][ni][c] = 0.f;

        #pragma unroll
        for (int ks = 0; ks < 16; ks++) {
            const int kb = ks * 8;
            uint32_t a[2][4], kbf[4][2];
            #pragma unroll
            for (int mi = 0; mi < 2; mi++) {
                const int rb = warp_m * 32 + mi * 16;
                a[mi][0] = __float_as_uint(Qs[(rb + g)     * QS_S + kb + tg]);
                a[mi][1] = __float_as_uint(Qs[(rb + 8 + g) * QS_S + kb + tg]);
                a[mi][2] = __float_as_uint(Qs[(rb + g)     * QS_S + kb + 4 + tg]);
                a[mi][3] = __float_as_uint(Qs[(rb + 8 + g) * QS_S + kb + 4 + tg]);
            }
            #pragma unroll
            for (int ni = 0; ni < 4; ni++) {
                const int key = warp_n * 32 + ni * 8 + g;
                kbf[ni][0] = __float_as_uint(Ks[key * KS_S + kb + tg]);
                kbf[ni][1] = __float_as_uint(Ks[key * KS_S + kb + 4 + tg]);
            }
            #pragma unroll
            for (int mi = 0; mi < 2; mi++)
                #pragma unroll
                for (int ni = 0; ni < 4; ni++)
                    mma_tf32(s[mi][ni], a[mi], kbf[ni]);
        }

        // mask + store S to smem (fp32)
        const bool diag = (k0 + A_BN - 1 > q0);
        #pragma unroll
        for (int mi = 0; mi < 2; mi++) {
            #pragma unroll
            for (int ni = 0; ni < 4; ni++) {
                const int r0  = warp_m * 32 + mi * 16 + g;
                const int col = warp_n * 32 + ni * 8 + tg * 2;
                float c0 = s[mi][ni][0], c1 = s[mi][ni][1];
                float c2 = s[mi][ni][2], c3 = s[mi][ni][3];
                if (diag) {
                    const int kc = k0 + col, qa = q0 + r0, qb = qa + 8;
                    if (kc     > qa) c0 = -1e30f;
                    if (kc + 1 > qa) c1 = -1e30f;
                    if (kc     > qb) c2 = -1e30f;
                    if (kc + 1 > qb) c3 = -1e30f;
                }
                *(float2*)&Ss[r0 * SS_S + col]       = make_float2(c0, c1);
                *(float2*)&Ss[(r0 + 8) * SS_S + col] = make_float2(c2, c3);
            }
        }
        __syncthreads();

        // ---- online softmax: each warp owns 16 rows; exp stored as tf32 ----
        #pragma unroll
        for (int rr = 0; rr < 16; rr++) {
            const int row = wid * 16 + rr;
            float x0 = Ss[row * SS_S + lane];
            float x1 = Ss[row * SS_S + 32 + lane];
            float mx = fmaxf(x0, x1);
            #pragma unroll
            for (int off = 16; off > 0; off >>= 1)
                mx = fmaxf(mx, __shfl_xor_sync(0xFFFFFFFFu, mx, off));
            const float m_old = m_s[row];
            const float m_new = fmaxf(m_old, mx);
            const float e0 = __expf(x0 - m_new);
            const float e1 = __expf(x1 - m_new);
            Ss[row * SS_S + lane]      = __uint_as_float(f2tf32(e0));
            Ss[row * SS_S + 32 + lane] = __uint_as_float(f2tf32(e1));
            float sum = e0 + e1;
            #pragma unroll
            for (int off = 16; off > 0; off >>= 1)
                sum += __shfl_xor_sync(0xFFFFFFFFu, sum, off);
            if (lane == 0) {
                const float alpha = __expf(m_old - m_new);
                alpha_s[row] = alpha;
                l_s[row]     = l_s[row] * alpha + sum;
                m_s[row]     = m_new;
            }
        }
        __syncthreads();

        // ---- rescale O, then O += P V via tf32 mma (warp tile 32x64) ----
        #pragma unroll
        for (int mi = 0; mi < 2; mi++) {
            const float al0 = alpha_s[warp_m * 32 + mi * 16 + g];
            const float al1 = alpha_s[warp_m * 32 + mi * 16 + 8 + g];
            #pragma unroll
            for (int ni = 0; ni < 8; ni++) {
                o[mi][ni][0] *= al0; o[mi][ni][1] *= al0;
                o[mi][ni][2] *= al1; o[mi][ni][3] *= al1;
            }
        }
        #pragma unroll
        for (int ks = 0; ks < 8; ks++) {
            const int kb = ks * 8;
            uint32_t a[2][4], vb[8][2];
            #pragma unroll
            for (int mi = 0; mi < 2; mi++) {
                const int rb = warp_m * 32 + mi * 16;
                a[mi][0] = __float_as_uint(Ss[(rb + g)     * SS_S + kb + tg]);
                a[mi][1] = __float_as_uint(Ss[(rb + 8 + g) * SS_S + kb + tg]);
                a[mi][2] = __float_as_uint(Ss[(rb + g)     * SS_S + kb + 4 + tg]);
                a[mi][3] = __float_as_uint(Ss[(rb + 8 + g) * SS_S + kb + 4 + tg]);
            }
            #pragma unroll
            for (int ni = 0; ni < 8; ni++) {
                const int col = warp_n * 64 + ni * 8 + g;
                vb[ni][0] = __float_as_uint(Vs[(kb + tg)     * VS_S + col]);
                vb[ni][1] = __float_as_uint(Vs[(kb + 4 + tg) * VS_S + col]);
            }
            #pragma unroll
            for (int mi = 0; mi < 2; mi++)
                #pragma unroll
                for (int ni = 0; ni < 8; ni++)
                    mma_tf32(o[mi][ni], a[mi], vb[ni]);
        }
        __syncthreads();   // before next tile overwrites Ks/Vs/Ss
    }

    // store partial (unnormalized O + m + l)
    const int slot = (b * AQT + qt) * MAXCH + ci;
    float* pbase = g_pacc + (size_t)slot * (128 * 128);
    #pragma unroll
    for (int mi = 0; mi < 2; mi++) {
        #pragma unroll
        for (int ni = 0; ni < 8; ni++) {
            const int row = warp_m * 32 + mi * 16 + g;
            const int col = warp_n * 64 + ni * 8 + tg * 2;
            *(float2*)&pbase[row * 128 + col] =
                make_float2(o[mi][ni][0], o[mi][ni][1]);
            *(float2*)&pbase[(row + 8) * 128 + col] =
                make_float2(o[mi][ni][2], o[mi][ni][3]);
        }
    }
    if (tid < 128) {
        g_pm[slot * 128 + tid] = m_s[tid];
        g_pl[slot * 128 + tid] = l_s[tid];
    }
}

// ======================= combine partials ===================================
__global__ __launch_bounds__(256) void combine_kernel(float* __restrict__ out)
{
    const int qt = blockIdx.x;     // 0..15
    const int b  = blockIdx.y;     // 0..3
    const int nch = (2 * qt + 5) >> 2;          // ceil((2qt+2)/4)
    const int slot0 = (b * AQT + qt) * MAXCH;
    const int q0 = qt * A_BM;

    __shared__ float w[MAXCH][128];

    const int tid = threadIdx.x;
    if (tid < 128) {
        const int row = tid;
        float M = -1e30f;
        for (int i = 0; i < nch; i++)
            M = fmaxf(M, g_pm[(slot0 + i) * 128 + row]);
        float L = 0.f;
        for (int i = 0; i < nch; i++)
            L += g_pl[(slot0 + i) * 128 + row] *
                 __expf(g_pm[(slot0 + i) * 128 + row] - M);
        const float invL = 1.f / L;
        for (int i = 0; i < nch; i++)
            w[i][row] = __expf(g_pm[(slot0 + i) * 128 + row] - M) * invL;
    }
    __syncthreads();

    const int c4    = (tid & 31) * 4;
    const int rbase = (tid >> 5) * 16;
    #pragma unroll
    for (int rr = 0; rr < 16; rr++) {
        const int row = rbase + rr;
        float4 o = make_float4(0.f, 0.f, 0.f, 0.f);
        for (int i = 0; i < nch; i++) {
            const float4 pa = *(const float4*)
                &g_pacc[(size_t)(slot0 + i) * (128 * 128) + row * 128 + c4];
            const float wi = w[i][row];
            o.x += wi * pa.x; o.y += wi * pa.y;
            o.z += wi * pa.z; o.w += wi * pa.w;
        }
        *(float4*)&out[((size_t)b * SEQ + q0 + row) * HDIM + c4] = o;
    }
}

// ======================= launch =============================================
extern "C" void kernel_launch(void* const* d_in, const int* in_sizes, int n_in,
                              void* d_out, int out_size)
{
    const float* x  = (const float*)d_in[0];
    const float* Wq = (const float*)d_in[1];
    const float* Wk = (const float*)d_in[2];
    const float* Wv = (const float*)d_in[3];
    float* out = (float*)d_out;

    static bool attr_set = false;
    if (!attr_set) {
        cudaFuncSetAttribute(attn_kernel,
                             cudaFuncAttributeMaxDynamicSharedMemorySize,
                             ASMEM_BYTES);
        attr_set = true;
    }

    // QKV projections (tf32 tensor): 128 M-tiles x 3 weights = 384 CTAs
    dim3 pgrid(BATCH * SEQ / 64, 3);
    proj_kernel<<<pgrid, 256>>>(x, Wq, Wk, Wv);

    // attention chunks: (qt, chunk, batch); inactive chunks exit immediately
    dim3 agrid(AQT, MAXCH, BATCH);
    attn_kernel<<<agrid, 256, ASMEM_BYTES>>>();

    // combine
    dim3 cgrid(AQT, BATCH);
    combine_kernel<<<cgrid, 256>>>(out);
}